// round 6
// baseline (speedup 1.0000x reference)
#include <cuda_runtime.h>

// ---------------------------------------------------------------------------
// EDeeperGCN edge classifier, factorized:
//   A = x @ W1[:128] + b1   (per node)      k1
//   B = x @ W1[128:]        (per node)      k1
//   out[e] = relu(A[src[e]] + B[dst[e]]) @ W2 + b2        k2
//
// Factorization: cat(x_s, x_d) @ W1 == x_s @ W1[:H] + x_d @ W1[H:], so the
// big GEMM moves from per-edge (640K rows) to per-node (10K rows): 66x less
// FMA work. k2 is then L2-bandwidth bound on the A/B row gathers (~655 MB of
// L2 reads; A,B are 5 MB each and stay L2-resident on the 126 MB L2).
// ---------------------------------------------------------------------------

#define HID 128
#define NOUT 10
#define MAX_NODES 10016
#define K1_ROWS 80
#define K2_TILE 128
#define HP 132              // padded H pitch (floats): 128+4, kills bank conflicts

__device__ float g_A[MAX_NODES * HID];
__device__ float g_B[MAX_NODES * HID];
__device__ int g_idx64;

// --------------------------------------------------------------------------
// detect whether edge_index buffer is int64 or int32.
// Node ids < 10000 < 2^32, so genuine int64 words are always < 2^32.
// If the buffer is int32, a u64 word holds (v0, v1) and is >= 2^32 whenever
// the odd-position value v1 != 0. Sample 64 words spread across the buffer.
// --------------------------------------------------------------------------
__global__ void detect_kernel(const unsigned long long* __restrict__ p,
                              int n_edges) {
    if (threadIdx.x == 0) {
        // If int64: buffer has 2*n_edges u64 words; if int32: n_edges words.
        // Sampling within the first n_edges words is safe for both.
        int stride = n_edges > 64 ? n_edges / 64 : 1;
        int is64 = 1;
        for (int i = 0; i < 64; i++)
            if (p[(long)i * stride] >= (1ULL << 32)) is64 = 0;
        g_idx64 = is64;
    }
}

// --------------------------------------------------------------------------
// k1: node GEMM  x[rows,128] @ W'[128,256] -> A (cols 0..127, +b1), B (128..255)
// 256 threads, 80 rows per CTA. W' fully staged in smem (128 KB), x tile 40 KB.
// Register tile: 10 rows x 8 cols per thread, rows packed pairwise into
// fma.rn.f32x2 (2x FMA throughput; ptxas never emits FFMA2 from plain C++).
// --------------------------------------------------------------------------
__global__ void __launch_bounds__(256, 1)
k1_kernel(const float* __restrict__ x, const float* __restrict__ W1,
          const float* __restrict__ b1, int n_nodes) {
    extern __shared__ float sm[];
    float* Ws = sm;                 // [128][256]  Ws[k][c]
    float* Xs = sm + 128 * 256;     // [80][128]   Xs[r][k]
    const int tid = threadIdx.x;

    // stage W' : c<128 -> W1[k][c], c>=128 -> W1[k+128][c-128]
    for (int v = tid; v < 8192; v += 256) {
        int f = v << 2;
        int k = f >> 8;
        int c = f & 255;
        float4 val = (c < 128)
            ? *(const float4*)(W1 + k * 128 + c)
            : *(const float4*)(W1 + (k + 128) * 128 + (c - 128));
        *(float4*)(Ws + f) = val;
    }
    const int rows0 = blockIdx.x * K1_ROWS;
    for (int v = tid; v < (K1_ROWS * 128) / 4; v += 256) {
        int f = v << 2;
        int r = f >> 7;
        int k = f & 127;
        float4 val = make_float4(0.f, 0.f, 0.f, 0.f);
        if (rows0 + r < n_nodes)
            val = *(const float4*)(x + (long)(rows0 + r) * 128 + k);
        *(float4*)(Xs + f) = val;
    }
    __syncthreads();

    const int tx = tid & 31;        // column lane: cols tx + 32*j
    const int ty = tid >> 5;        // row octet: rows ty*10 .. ty*10+9
    const int rbase = ty * 10;

    unsigned long long acc[5][8];
    #pragma unroll
    for (int j = 0; j < 8; j++) {
        unsigned long long init = 0ULL;
        if (j < 4) {
            unsigned u = __float_as_uint(__ldg(b1 + tx + 32 * j));
            asm("mov.b64 %0, {%1, %1};" : "=l"(init) : "r"(u));
        }
        #pragma unroll
        for (int p = 0; p < 5; p++) acc[p][j] = init;
    }

    #pragma unroll 2
    for (int k = 0; k < 128; k++) {
        unsigned long long xp[5];
        #pragma unroll
        for (int p = 0; p < 5; p++) {
            unsigned x0 = __float_as_uint(Xs[(rbase + 2 * p) * 128 + k]);
            unsigned x1 = __float_as_uint(Xs[(rbase + 2 * p + 1) * 128 + k]);
            asm("mov.b64 %0, {%1, %2};" : "=l"(xp[p]) : "r"(x0), "r"(x1));
        }
        #pragma unroll
        for (int j = 0; j < 8; j++) {
            unsigned wu = __float_as_uint(Ws[(k << 8) + tx + (j << 5)]);
            unsigned long long wd;
            asm("mov.b64 %0, {%1, %1};" : "=l"(wd) : "r"(wu));
            #pragma unroll
            for (int p = 0; p < 5; p++)
                asm("fma.rn.f32x2 %0, %1, %2, %0;"
                    : "+l"(acc[p][j]) : "l"(xp[p]), "l"(wd));
        }
    }

    // writeback
    #pragma unroll
    for (int p = 0; p < 5; p++) {
        int g0 = rows0 + rbase + 2 * p;
        #pragma unroll
        for (int j = 0; j < 8; j++) {
            unsigned lo, hi;
            asm("mov.b64 {%0, %1}, %2;" : "=r"(lo), "=r"(hi) : "l"(acc[p][j]));
            float* dst = (j < 4) ? g_A : g_B;
            int c = tx + ((j & 3) << 5);
            if (g0 < n_nodes)     dst[(long)g0 * 128 + c]       = __uint_as_float(lo);
            if (g0 + 1 < n_nodes) dst[(long)(g0 + 1) * 128 + c] = __uint_as_float(hi);
        }
    }
}

// --------------------------------------------------------------------------
// k2: per-edge  h = relu(A[src]+B[dst]);  out = h @ W2 + b2
// 128 threads / 128-edge tile.
// Phase A: warp-per-edge coalesced full-row gather; lane l handles features
//          4l..4l+3 and writes ONE STS.128 into Hs[e][4l] (pitch HP=132:
//          byte 528*e + 16*l -> banks 4l..4l+3 tile all 32 banks per 8-lane
//          phase; conflict-free).
// Phase B: thread-per-edge reads its own Hs row with 32 LDS.128 (pitch 132
//          == 4 mod 32 -> distinct banks per 8-lane phase, conflict-free),
//          W2 pre-paired in smem as W2p[p][j] = (W2[j][2p], W2[j][2p+1]) and
//          read as warp-broadcast ulonglong2 (2 j at a time); 5 f32x2 FMA
//          pairs per j.
// --------------------------------------------------------------------------
__global__ void __launch_bounds__(128, 3)
k2_kernel(const void* __restrict__ eidx, const float* __restrict__ W2,
          const float* __restrict__ b2, float* __restrict__ out, int n_edges) {
    extern __shared__ float sm[];
    float* Hs = sm;                           // [128][HP]
    unsigned long long* W2p =
        (unsigned long long*)(sm + K2_TILE * HP);  // [5][128] u64 pairs
    int* sidx = (int*)(W2p + 5 * 128);
    int* didx = sidx + K2_TILE;
    const int tid = threadIdx.x;

    // pre-pair W2: W2p[p*128 + j] = (W2[j*10+2p], W2[j*10+2p+1])
    for (int i = tid; i < 5 * 128; i += 128) {
        int p = i >> 7, j = i & 127;
        unsigned u0 = __float_as_uint(W2[j * 10 + 2 * p]);
        unsigned u1 = __float_as_uint(W2[j * 10 + 2 * p + 1]);
        unsigned long long w;
        asm("mov.b64 %0, {%1, %2};" : "=l"(w) : "r"(u0), "r"(u1));
        W2p[i] = w;
    }

    const int e0 = blockIdx.x << 7;
    {
        int e = e0 + tid;
        int s = 0, d = 0;
        if (e < n_edges) {
            if (g_idx64) {
                const long long* p = (const long long*)eidx;
                s = (int)p[e]; d = (int)p[n_edges + e];
            } else {
                const int* p = (const int*)eidx;
                s = p[e]; d = p[n_edges + e];
            }
        }
        sidx[tid] = s; didx[tid] = d;
    }
    __syncthreads();

    // phase A: gather + relu -> Hs[e][4l..4l+3], one STS.128 per (lane, edge)
    {
        const int w = tid >> 5, l = tid & 31;
        #pragma unroll 4
        for (int ee = 0; ee < 32; ee++) {
            int el = (w << 5) + ee;
            int s = sidx[el], d = didx[el];
            float4 a = *(const float4*)(g_A + ((long)s << 7) + (l << 2));
            float4 b = *(const float4*)(g_B + ((long)d << 7) + (l << 2));
            float4 h;
            h.x = fmaxf(a.x + b.x, 0.f);
            h.y = fmaxf(a.y + b.y, 0.f);
            h.z = fmaxf(a.z + b.z, 0.f);
            h.w = fmaxf(a.w + b.w, 0.f);
            *(float4*)(Hs + el * HP + (l << 2)) = h;
        }
    }
    __syncthreads();

    // phase B: tiny GEMV per edge
    unsigned long long acc[5];
    #pragma unroll
    for (int p = 0; p < 5; p++) {
        unsigned u0 = __float_as_uint(__ldg(b2 + 2 * p));
        unsigned u1 = __float_as_uint(__ldg(b2 + 2 * p + 1));
        asm("mov.b64 %0, {%1, %2};" : "=l"(acc[p]) : "r"(u0), "r"(u1));
    }
    const float* hrow = Hs + tid * HP;
    const ulonglong2* W2v = (const ulonglong2*)W2p;   // [5][64] of (j,j+1) pairs
    #pragma unroll 8
    for (int t = 0; t < 32; t++) {                    // j = 4t..4t+3
        float4 h4 = *(const float4*)(hrow + (t << 2));
        unsigned long long hh[4];
        asm("mov.b64 %0, {%1, %1};" : "=l"(hh[0]) : "r"(__float_as_uint(h4.x)));
        asm("mov.b64 %0, {%1, %1};" : "=l"(hh[1]) : "r"(__float_as_uint(h4.y)));
        asm("mov.b64 %0, {%1, %1};" : "=l"(hh[2]) : "r"(__float_as_uint(h4.z)));
        asm("mov.b64 %0, {%1, %1};" : "=l"(hh[3]) : "r"(__float_as_uint(h4.w)));
        #pragma unroll
        for (int p = 0; p < 5; p++) {
            ulonglong2 w01 = W2v[(p << 6) + 2 * t];       // j=4t, 4t+1
            ulonglong2 w23 = W2v[(p << 6) + 2 * t + 1];   // j=4t+2, 4t+3
            asm("fma.rn.f32x2 %0, %1, %2, %0;" : "+l"(acc[p]) : "l"(hh[0]), "l"(w01.x));
            asm("fma.rn.f32x2 %0, %1, %2, %0;" : "+l"(acc[p]) : "l"(hh[1]), "l"(w01.y));
            asm("fma.rn.f32x2 %0, %1, %2, %0;" : "+l"(acc[p]) : "l"(hh[2]), "l"(w23.x));
            asm("fma.rn.f32x2 %0, %1, %2, %0;" : "+l"(acc[p]) : "l"(hh[3]), "l"(w23.y));
        }
    }

    int e = e0 + tid;
    if (e < n_edges) {
        float* op = out + (long)e * 10;   // 40*e bytes -> 8B aligned
        #pragma unroll
        for (int p = 0; p < 5; p++)
            *(unsigned long long*)(op + 2 * p) = acc[p];
    }
}

// --------------------------------------------------------------------------
extern "C" void kernel_launch(void* const* d_in, const int* in_sizes, int n_in,
                              void* d_out, int out_size) {
    const float* x  = (const float*)d_in[0];
    const void* eix = d_in[1];
    const float* W1 = (const float*)d_in[2];
    const float* b1 = (const float*)d_in[3];
    const float* W2 = (const float*)d_in[4];
    const float* b2 = (const float*)d_in[5];
    float* out = (float*)d_out;

    int n_nodes = in_sizes[0] / HID;
    int n_edges = in_sizes[1] / 2;

    const int K1_SMEM = (128 * 256 + K1_ROWS * 128) * 4;           // 168 KB
    const int K2_SMEM = K2_TILE * HP * 4 + 5 * 128 * 8 + K2_TILE * 8; // 72 KB

    cudaFuncSetAttribute(k1_kernel, cudaFuncAttributeMaxDynamicSharedMemorySize, K1_SMEM);
    cudaFuncSetAttribute(k2_kernel, cudaFuncAttributeMaxDynamicSharedMemorySize, K2_SMEM);

    detect_kernel<<<1, 32>>>((const unsigned long long*)eix, n_edges);
    k1_kernel<<<(n_nodes + K1_ROWS - 1) / K1_ROWS, 256, K1_SMEM>>>(x, W1, b1, n_nodes);
    k2_kernel<<<(n_edges + K2_TILE - 1) / K2_TILE, K2_TILE, K2_SMEM>>>(eix, W2, b2, out, n_edges);
}

// round 8
// speedup vs baseline: 1.3133x; 1.3133x over previous
#include <cuda_runtime.h>

// ---------------------------------------------------------------------------
// EDeeperGCN edge classifier, factorized:
//   A = x @ W1[:128] + b1   (per node)      k1
//   B = x @ W1[128:]        (per node)      k1
//   out[e] = relu(A[src[e]] + B[dst[e]]) @ W2 + b2        k2
//
// R6 result: 170.5us pass. This round: parallel detect (5.9 -> ~1us), k2
// two-pass feature split (smem 72KB -> 40KB, 3 -> 5 CTAs/SM, 12 -> 20
// warps/SM) to attack gather latency, launch order k1->detect->k2 so ncu
// (-s 5) captures k2 next time.
// ---------------------------------------------------------------------------

#define HID 128
#define NOUT 10
#define MAX_NODES 10016
#define K1_ROWS 80
#define K2_TILE 128
#define HP 66               // per-pass H pitch (floats): 64 + 2 pad

__device__ float g_A[MAX_NODES * HID];
__device__ float g_B[MAX_NODES * HID];
__device__ int g_idx64;

// --------------------------------------------------------------------------
// detect int64 vs int32 edge_index storage. 64 parallel strided samples;
// any u64 word >= 2^32 proves int32 packing (node ids < 10000 < 2^32).
// --------------------------------------------------------------------------
__global__ void detect_kernel(const unsigned long long* __restrict__ p,
                              int n_edges) {
    int tid = threadIdx.x;              // 64 threads
    long stride = n_edges > 64 ? n_edges / 64 : 1;
    int big = 0;
    long w = (long)tid * stride;
    if (w < n_edges) big = (p[w] >= (1ULL << 32));
    int any32 = __syncthreads_or(big);
    if (tid == 0) g_idx64 = any32 ? 0 : 1;
}

// --------------------------------------------------------------------------
// k1: node GEMM  x[rows,128] @ W'[128,256] -> A (cols 0..127, +b1), B (128..255)
// 256 threads, 80 rows per CTA. W' fully staged in smem (128 KB), x tile 40 KB.
// Register tile: 10 rows x 8 cols per thread, rows packed pairwise into
// fma.rn.f32x2 (2x FMA throughput; ptxas never emits FFMA2 from plain C++).
// --------------------------------------------------------------------------
__global__ void __launch_bounds__(256, 1)
k1_kernel(const float* __restrict__ x, const float* __restrict__ W1,
          const float* __restrict__ b1, int n_nodes) {
    extern __shared__ float sm[];
    float* Ws = sm;                 // [128][256]  Ws[k][c]
    float* Xs = sm + 128 * 256;     // [80][128]   Xs[r][k]
    const int tid = threadIdx.x;

    for (int v = tid; v < 8192; v += 256) {
        int f = v << 2;
        int k = f >> 8;
        int c = f & 255;
        float4 val = (c < 128)
            ? *(const float4*)(W1 + k * 128 + c)
            : *(const float4*)(W1 + (k + 128) * 128 + (c - 128));
        *(float4*)(Ws + f) = val;
    }
    const int rows0 = blockIdx.x * K1_ROWS;
    for (int v = tid; v < (K1_ROWS * 128) / 4; v += 256) {
        int f = v << 2;
        int r = f >> 7;
        int k = f & 127;
        float4 val = make_float4(0.f, 0.f, 0.f, 0.f);
        if (rows0 + r < n_nodes)
            val = *(const float4*)(x + (long)(rows0 + r) * 128 + k);
        *(float4*)(Xs + f) = val;
    }
    __syncthreads();

    const int tx = tid & 31;        // column lane: cols tx + 32*j
    const int ty = tid >> 5;        // row octet: rows ty*10 .. ty*10+9
    const int rbase = ty * 10;

    unsigned long long acc[5][8];
    #pragma unroll
    for (int j = 0; j < 8; j++) {
        unsigned long long init = 0ULL;
        if (j < 4) {
            unsigned u = __float_as_uint(__ldg(b1 + tx + 32 * j));
            asm("mov.b64 %0, {%1, %1};" : "=l"(init) : "r"(u));
        }
        #pragma unroll
        for (int p = 0; p < 5; p++) acc[p][j] = init;
    }

    #pragma unroll 2
    for (int k = 0; k < 128; k++) {
        unsigned long long xp[5];
        #pragma unroll
        for (int p = 0; p < 5; p++) {
            unsigned x0 = __float_as_uint(Xs[(rbase + 2 * p) * 128 + k]);
            unsigned x1 = __float_as_uint(Xs[(rbase + 2 * p + 1) * 128 + k]);
            asm("mov.b64 %0, {%1, %2};" : "=l"(xp[p]) : "r"(x0), "r"(x1));
        }
        #pragma unroll
        for (int j = 0; j < 8; j++) {
            unsigned wu = __float_as_uint(Ws[(k << 8) + tx + (j << 5)]);
            unsigned long long wd;
            asm("mov.b64 %0, {%1, %1};" : "=l"(wd) : "r"(wu));
            #pragma unroll
            for (int p = 0; p < 5; p++)
                asm("fma.rn.f32x2 %0, %1, %2, %0;"
                    : "+l"(acc[p][j]) : "l"(xp[p]), "l"(wd));
        }
    }

    #pragma unroll
    for (int p = 0; p < 5; p++) {
        int g0 = rows0 + rbase + 2 * p;
        #pragma unroll
        for (int j = 0; j < 8; j++) {
            unsigned lo, hi;
            asm("mov.b64 {%0, %1}, %2;" : "=r"(lo), "=r"(hi) : "l"(acc[p][j]));
            float* dst = (j < 4) ? g_A : g_B;
            int c = tx + ((j & 3) << 5);
            if (g0 < n_nodes)     dst[(long)g0 * 128 + c]       = __uint_as_float(lo);
            if (g0 + 1 < n_nodes) dst[(long)(g0 + 1) * 128 + c] = __uint_as_float(hi);
        }
    }
}

// --------------------------------------------------------------------------
// k2: per-edge  h = relu(A[src]+B[dst]);  out = h @ W2 + b2
// 128 threads / 128-edge tile, TWO feature passes of 64 (smem 40KB -> 5
// CTAs/SM, 20 warps/SM for gather-latency cover).
// Phase A (per pass): warp-per-edge; lane l loads float2 of features
//   fbase+2l..2l+1 from A[s] and B[d] (256B/warp/row, coalesced), batched 4
//   edges for MLP=8. STS.64 into Hs[e][2l]: lane l touches banks 2l,2l+1 per
//   16-lane wavefront phase -> all 32 banks once, conflict-free.
// Phase B (per pass): thread-per-edge; LDS.64 of own row (banks (2tid+2t)
//   mod 32, distinct per 16-lane phase), W2 pre-paired u64 broadcast loads,
//   2 f32x2 FMA per (t, output-pair). Accumulators live across passes.
// --------------------------------------------------------------------------
__global__ void __launch_bounds__(128, 5)
k2_kernel(const void* __restrict__ eidx, const float* __restrict__ W2,
          const float* __restrict__ b2, float* __restrict__ out, int n_edges) {
    extern __shared__ float sm[];
    float* Hs = sm;                                      // [128][HP]
    unsigned long long* W2p =
        (unsigned long long*)(sm + K2_TILE * HP);        // [5][128] u64 pairs
    int* sidx = (int*)(W2p + 5 * 128);
    int* didx = sidx + K2_TILE;
    const int tid = threadIdx.x;

    // pre-pair W2: W2p[p*128 + j] = (W2[j*10+2p], W2[j*10+2p+1])
    for (int i = tid; i < 5 * 128; i += 128) {
        int p = i >> 7, j = i & 127;
        unsigned u0 = __float_as_uint(W2[j * 10 + 2 * p]);
        unsigned u1 = __float_as_uint(W2[j * 10 + 2 * p + 1]);
        unsigned long long w;
        asm("mov.b64 %0, {%1, %2};" : "=l"(w) : "r"(u0), "r"(u1));
        W2p[i] = w;
    }

    const int e0 = blockIdx.x << 7;
    {
        int e = e0 + tid;
        int s = 0, d = 0;
        if (e < n_edges) {
            if (g_idx64) {
                const long long* p = (const long long*)eidx;
                s = (int)p[e]; d = (int)p[n_edges + e];
            } else {
                const int* p = (const int*)eidx;
                s = p[e]; d = p[n_edges + e];
            }
        }
        sidx[tid] = s; didx[tid] = d;
    }
    __syncthreads();

    unsigned long long acc[5];
    #pragma unroll
    for (int p = 0; p < 5; p++) {
        unsigned u0 = __float_as_uint(__ldg(b2 + 2 * p));
        unsigned u1 = __float_as_uint(__ldg(b2 + 2 * p + 1));
        asm("mov.b64 %0, {%1, %2};" : "=l"(acc[p]) : "r"(u0), "r"(u1));
    }

    const int w = tid >> 5, l = tid & 31;
    const ulonglong2* W2v = (const ulonglong2*)W2p;   // [5][64] (j,j+1) pairs

    #pragma unroll
    for (int pass = 0; pass < 2; pass++) {
        const int fbase = pass << 6;

        // phase A: gather + relu this pass's 64 features, 4-edge batches
        #pragma unroll
        for (int eo = 0; eo < 32; eo += 4) {
            float2 av[4], bv[4];
            #pragma unroll
            for (int u = 0; u < 4; u++) {
                int el = (w << 5) + eo + u;
                int s = sidx[el], d = didx[el];
                av[u] = *(const float2*)(g_A + ((long)s << 7) + fbase + (l << 1));
                bv[u] = *(const float2*)(g_B + ((long)d << 7) + fbase + (l << 1));
            }
            #pragma unroll
            for (int u = 0; u < 4; u++) {
                int el = (w << 5) + eo + u;
                float2 h;
                h.x = fmaxf(av[u].x + bv[u].x, 0.f);
                h.y = fmaxf(av[u].y + bv[u].y, 0.f);
                *(float2*)(Hs + el * HP + (l << 1)) = h;
            }
        }
        __syncthreads();

        // phase B: accumulate this pass's 64 features
        const float* hrow = Hs + tid * HP;
        const int jp0 = pass << 5;          // pair index base (j = 2*jp)
        #pragma unroll 8
        for (int t = 0; t < 32; t++) {
            float2 h2 = *(const float2*)(hrow + (t << 1));
            unsigned long long hh0, hh1;
            asm("mov.b64 %0, {%1, %1};" : "=l"(hh0) : "r"(__float_as_uint(h2.x)));
            asm("mov.b64 %0, {%1, %1};" : "=l"(hh1) : "r"(__float_as_uint(h2.y)));
            #pragma unroll
            for (int p = 0; p < 5; p++) {
                ulonglong2 wv = W2v[(p << 6) + jp0 + t];  // pairs for j, j+1
                asm("fma.rn.f32x2 %0, %1, %2, %0;" : "+l"(acc[p]) : "l"(hh0), "l"(wv.x));
                asm("fma.rn.f32x2 %0, %1, %2, %0;" : "+l"(acc[p]) : "l"(hh1), "l"(wv.y));
            }
        }
        if (pass == 0) __syncthreads();     // protect Hs before pass-1 phase A
    }

    int e = e0 + tid;
    if (e < n_edges) {
        float* op = out + (long)e * 10;     // 40*e bytes -> 8B aligned
        #pragma unroll
        for (int p = 0; p < 5; p++)
            *(unsigned long long*)(op + 2 * p) = acc[p];
    }
}

// --------------------------------------------------------------------------
extern "C" void kernel_launch(void* const* d_in, const int* in_sizes, int n_in,
                              void* d_out, int out_size) {
    const float* x  = (const float*)d_in[0];
    const void* eix = d_in[1];
    const float* W1 = (const float*)d_in[2];
    const float* b1 = (const float*)d_in[3];
    const float* W2 = (const float*)d_in[4];
    const float* b2 = (const float*)d_in[5];
    float* out = (float*)d_out;

    int n_nodes = in_sizes[0] / HID;
    int n_edges = in_sizes[1] / 2;

    const int K1_SMEM = (128 * 256 + K1_ROWS * 128) * 4;              // 168 KB
    const int K2_SMEM = K2_TILE * HP * 4 + 5 * 128 * 8 + K2_TILE * 8; // ~40 KB

    cudaFuncSetAttribute(k1_kernel, cudaFuncAttributeMaxDynamicSharedMemorySize, K1_SMEM);
    cudaFuncSetAttribute(k2_kernel, cudaFuncAttributeMaxDynamicSharedMemorySize, K2_SMEM);

    // order k1 -> detect -> k2: k1 has no dependency on g_idx64, and this
    // makes ncu's "-s 5" land on k2 (launch index 5) next profile.
    k1_kernel<<<(n_nodes + K1_ROWS - 1) / K1_ROWS, 256, K1_SMEM>>>(x, W1, b1, n_nodes);
    detect_kernel<<<1, 64>>>((const unsigned long long*)eix, n_edges);
    k2_kernel<<<(n_edges + K2_TILE - 1) / K2_TILE, K2_TILE, K2_SMEM>>>(eix, W2, b2, out, n_edges);
}

// round 9
// speedup vs baseline: 1.3868x; 1.0560x over previous
#include <cuda_runtime.h>

// ---------------------------------------------------------------------------
// EDeeperGCN edge classifier, factorized:
//   A = x @ W1[:128] + b1   (per node)      k1 (A-CTAs)
//   B = x @ W1[128:]        (per node)      k1 (B-CTAs)
//   out[e] = relu(A[src[e]] + B[dst[e]]) @ W2 + b2        k2
//
// R8: 129.8us. k1 profile: 36.3us, occ 12.6%, issue 44% -> latency-bound at
// 8 warps/SM + 23 idle SMs. This round: k1 split into per-half CTAs (smem
// 168KB -> 106KB, 2 CTAs/SM, 16 warps/SM, grid 250), Xs transposed [k][r]
// so row pairs load as one LDS.64 (inner loop 71 -> 33 instr/k).
// ---------------------------------------------------------------------------

#define HID 128
#define NOUT 10
#define MAX_NODES 10016
#define K1_ROWS 80
#define XP 82               // transposed Xs pitch (floats): 80 + 2 (even->8B ok)
#define K2_TILE 128
#define HP 66               // per-pass H pitch (floats): 64 + 2 pad

__device__ float g_A[MAX_NODES * HID];
__device__ float g_B[MAX_NODES * HID];
__device__ int g_idx64;

// --------------------------------------------------------------------------
// detect int64 vs int32 edge_index storage. 64 parallel strided samples;
// any u64 word >= 2^32 proves int32 packing (node ids < 10000 < 2^32).
// --------------------------------------------------------------------------
__global__ void detect_kernel(const unsigned long long* __restrict__ p,
                              int n_edges) {
    int tid = threadIdx.x;              // 64 threads
    long stride = n_edges > 64 ? n_edges / 64 : 1;
    int big = 0;
    long w = (long)tid * stride;
    if (w < n_edges) big = (p[w] >= (1ULL << 32));
    int any32 = __syncthreads_or(big);
    if (tid == 0) g_idx64 = any32 ? 0 : 1;
}

// --------------------------------------------------------------------------
// k1: half-GEMM per CTA. Grid = 2*nblk: block b < nblk computes A half
// (W1 rows 0..127, +b1) for rows b*80..; block b >= nblk computes B half
// (W1 rows 128..255). 256 threads; Ws [128][128] = 64 KB, Xs transposed
// [128][XP] = 42 KB -> 106 KB smem, 2 CTAs/SM.
// Thread (tx,ty): cols tx+32j (j=0..3), rows ty*10..ty*10+9 as 5 f32x2 pairs.
// Inner loop per k: 5 LDS.64 (row pairs, broadcast) + 4 LDS.32 (W) + 4 dup
// + 20 fma.rn.f32x2.
// --------------------------------------------------------------------------
__global__ void __launch_bounds__(256, 2)
k1_kernel(const float* __restrict__ x, const float* __restrict__ W1,
          const float* __restrict__ b1, int n_nodes, int nblk) {
    extern __shared__ float sm[];
    float* Ws = sm;                 // [128][128]  Ws[k][c]
    float* Xs = sm + 128 * 128;     // [128][XP]   Xs[k][r]  (transposed)
    const int tid = threadIdx.x;

    const int is_b = blockIdx.x >= nblk;
    const int blk = is_b ? blockIdx.x - nblk : blockIdx.x;
    const float* Wsrc = W1 + (is_b ? 128 * 128 : 0);   // W1 rows [128h,128h+128)

    // stage W half: 128x128 floats, coalesced float4
    for (int v = tid; v < 4096; v += 256)
        *(float4*)(Ws + (v << 2)) = *(const float4*)(Wsrc + (v << 2));

    // stage x tile transposed: Xs[k][r] = x[rows0+r][k]
    const int rows0 = blk * K1_ROWS;
    for (int idx = tid; idx < K1_ROWS * 128; idx += 256) {
        int r = idx >> 7;
        int k = idx & 127;
        float v = 0.f;
        if (rows0 + r < n_nodes) v = x[(long)(rows0 + r) * 128 + k];
        Xs[k * XP + r] = v;
    }
    __syncthreads();

    const int tx = tid & 31;        // col lane: cols tx + 32*j
    const int ty = tid >> 5;        // row group: rows ty*10 .. ty*10+9
    const int rbase = ty * 10;

    unsigned long long acc[5][4];
    #pragma unroll
    for (int j = 0; j < 4; j++) {
        unsigned long long init = 0ULL;
        if (!is_b) {
            unsigned u = __float_as_uint(__ldg(b1 + tx + 32 * j));
            asm("mov.b64 %0, {%1, %1};" : "=l"(init) : "r"(u));
        }
        #pragma unroll
        for (int p = 0; p < 5; p++) acc[p][j] = init;
    }

    #pragma unroll 4
    for (int k = 0; k < 128; k++) {
        unsigned long long xp[5];
        const float* xk = Xs + k * XP + rbase;
        #pragma unroll
        for (int p = 0; p < 5; p++)
            xp[p] = *(const unsigned long long*)(xk + 2 * p);   // LDS.64 pair
        #pragma unroll
        for (int j = 0; j < 4; j++) {
            unsigned wu = __float_as_uint(Ws[(k << 7) + tx + (j << 5)]);
            unsigned long long wd;
            asm("mov.b64 %0, {%1, %1};" : "=l"(wd) : "r"(wu));
            #pragma unroll
            for (int p = 0; p < 5; p++)
                asm("fma.rn.f32x2 %0, %1, %2, %0;"
                    : "+l"(acc[p][j]) : "l"(xp[p]), "l"(wd));
        }
    }

    float* dst = is_b ? g_B : g_A;
    #pragma unroll
    for (int p = 0; p < 5; p++) {
        int g0 = rows0 + rbase + 2 * p;
        #pragma unroll
        for (int j = 0; j < 4; j++) {
            unsigned lo, hi;
            asm("mov.b64 {%0, %1}, %2;" : "=r"(lo), "=r"(hi) : "l"(acc[p][j]));
            int c = tx + (j << 5);
            if (g0 < n_nodes)     dst[(long)g0 * 128 + c]       = __uint_as_float(lo);
            if (g0 + 1 < n_nodes) dst[(long)(g0 + 1) * 128 + c] = __uint_as_float(hi);
        }
    }
}

// --------------------------------------------------------------------------
// k2: per-edge  h = relu(A[src]+B[dst]);  out = h @ W2 + b2
// 128 threads / 128-edge tile, TWO feature passes of 64 (smem ~40KB, 5
// CTAs/SM, 20 warps/SM for gather-latency cover). Unchanged from R8.
// --------------------------------------------------------------------------
__global__ void __launch_bounds__(128, 5)
k2_kernel(const void* __restrict__ eidx, const float* __restrict__ W2,
          const float* __restrict__ b2, float* __restrict__ out, int n_edges) {
    extern __shared__ float sm[];
    float* Hs = sm;                                      // [128][HP]
    unsigned long long* W2p =
        (unsigned long long*)(sm + K2_TILE * HP);        // [5][128] u64 pairs
    int* sidx = (int*)(W2p + 5 * 128);
    int* didx = sidx + K2_TILE;
    const int tid = threadIdx.x;

    for (int i = tid; i < 5 * 128; i += 128) {
        int p = i >> 7, j = i & 127;
        unsigned u0 = __float_as_uint(W2[j * 10 + 2 * p]);
        unsigned u1 = __float_as_uint(W2[j * 10 + 2 * p + 1]);
        unsigned long long w;
        asm("mov.b64 %0, {%1, %2};" : "=l"(w) : "r"(u0), "r"(u1));
        W2p[i] = w;
    }

    const int e0 = blockIdx.x << 7;
    {
        int e = e0 + tid;
        int s = 0, d = 0;
        if (e < n_edges) {
            if (g_idx64) {
                const long long* p = (const long long*)eidx;
                s = (int)p[e]; d = (int)p[n_edges + e];
            } else {
                const int* p = (const int*)eidx;
                s = p[e]; d = p[n_edges + e];
            }
        }
        sidx[tid] = s; didx[tid] = d;
    }
    __syncthreads();

    unsigned long long acc[5];
    #pragma unroll
    for (int p = 0; p < 5; p++) {
        unsigned u0 = __float_as_uint(__ldg(b2 + 2 * p));
        unsigned u1 = __float_as_uint(__ldg(b2 + 2 * p + 1));
        asm("mov.b64 %0, {%1, %2};" : "=l"(acc[p]) : "r"(u0), "r"(u1));
    }

    const int w = tid >> 5, l = tid & 31;
    const ulonglong2* W2v = (const ulonglong2*)W2p;   // [5][64] (j,j+1) pairs

    #pragma unroll
    for (int pass = 0; pass < 2; pass++) {
        const int fbase = pass << 6;

        #pragma unroll
        for (int eo = 0; eo < 32; eo += 4) {
            float2 av[4], bv[4];
            #pragma unroll
            for (int u = 0; u < 4; u++) {
                int el = (w << 5) + eo + u;
                int s = sidx[el], d = didx[el];
                av[u] = *(const float2*)(g_A + ((long)s << 7) + fbase + (l << 1));
                bv[u] = *(const float2*)(g_B + ((long)d << 7) + fbase + (l << 1));
            }
            #pragma unroll
            for (int u = 0; u < 4; u++) {
                int el = (w << 5) + eo + u;
                float2 h;
                h.x = fmaxf(av[u].x + bv[u].x, 0.f);
                h.y = fmaxf(av[u].y + bv[u].y, 0.f);
                *(float2*)(Hs + el * HP + (l << 1)) = h;
            }
        }
        __syncthreads();

        const float* hrow = Hs + tid * HP;
        const int jp0 = pass << 5;
        #pragma unroll 8
        for (int t = 0; t < 32; t++) {
            float2 h2 = *(const float2*)(hrow + (t << 1));
            unsigned long long hh0, hh1;
            asm("mov.b64 %0, {%1, %1};" : "=l"(hh0) : "r"(__float_as_uint(h2.x)));
            asm("mov.b64 %0, {%1, %1};" : "=l"(hh1) : "r"(__float_as_uint(h2.y)));
            #pragma unroll
            for (int p = 0; p < 5; p++) {
                ulonglong2 wv = W2v[(p << 6) + jp0 + t];
                asm("fma.rn.f32x2 %0, %1, %2, %0;" : "+l"(acc[p]) : "l"(hh0), "l"(wv.x));
                asm("fma.rn.f32x2 %0, %1, %2, %0;" : "+l"(acc[p]) : "l"(hh1), "l"(wv.y));
            }
        }
        if (pass == 0) __syncthreads();
    }

    int e = e0 + tid;
    if (e < n_edges) {
        float* op = out + (long)e * 10;
        #pragma unroll
        for (int p = 0; p < 5; p++)
            *(unsigned long long*)(op + 2 * p) = acc[p];
    }
}

// --------------------------------------------------------------------------
extern "C" void kernel_launch(void* const* d_in, const int* in_sizes, int n_in,
                              void* d_out, int out_size) {
    const float* x  = (const float*)d_in[0];
    const void* eix = d_in[1];
    const float* W1 = (const float*)d_in[2];
    const float* b1 = (const float*)d_in[3];
    const float* W2 = (const float*)d_in[4];
    const float* b2 = (const float*)d_in[5];
    float* out = (float*)d_out;

    int n_nodes = in_sizes[0] / HID;
    int n_edges = in_sizes[1] / 2;
    int nblk = (n_nodes + K1_ROWS - 1) / K1_ROWS;        // 125

    const int K1_SMEM = (128 * 128 + 128 * XP) * 4;                   // ~106 KB
    const int K2_SMEM = K2_TILE * HP * 4 + 5 * 128 * 8 + K2_TILE * 8; // ~40 KB

    cudaFuncSetAttribute(k1_kernel, cudaFuncAttributeMaxDynamicSharedMemorySize, K1_SMEM);
    cudaFuncSetAttribute(k2_kernel, cudaFuncAttributeMaxDynamicSharedMemorySize, K2_SMEM);

    k1_kernel<<<2 * nblk, 256, K1_SMEM>>>(x, W1, b1, n_nodes, nblk);
    detect_kernel<<<1, 64>>>((const unsigned long long*)eix, n_edges);
    k2_kernel<<<(n_edges + K2_TILE - 1) / K2_TILE, K2_TILE, K2_SMEM>>>(eix, W2, b2, out, n_edges);
}